// round 5
// baseline (speedup 1.0000x reference)
#include <cuda_runtime.h>
#include <cstdint>
#include <math.h>

// Problem: B=4, T=4096, C=2048, E=64, K=8
#define NTOK   16384
#define CDIM   2048
#define NEXP   64
#define KTOP   8
#define BM     128
#define BK     32
#define NCHUNK (CDIM / BK)   // 64
#define NKTOT  (NTOK * KTOP)
#define NTHR   128

// smem: A [2][BK][132] floats, B [2][BK][68] floats; reused as logits [128][65]
#define APITCH 132
#define BPITCH 68
#define ABUF   (BK * APITCH)             // 4224 floats
#define BBUF   (BK * BPITCH)             // 2176 floats
#define AREG   (2 * ABUF)
#define SMEM_DYN ((AREG + 2 * BBUF) * 4) // 51200 bytes (>= 128*65*4 logits)

__device__ float g_counts[NEXP];
__device__ int   g_done = 0;

// --- packed fp32x2 helpers (B300: scalar FFMA is half-rate; f32x2 is full-rate) ---
__device__ __forceinline__ unsigned long long dup2(float x) {
    unsigned long long r;
    asm("mov.b64 %0, {%1, %1};" : "=l"(r) : "f"(x));
    return r;
}
__device__ __forceinline__ void fma2(unsigned long long& d, unsigned long long a, unsigned long long b) {
    asm("fma.rn.f32x2 %0, %1, %2, %0;" : "+l"(d) : "l"(a), "l"(b));
}
__device__ __forceinline__ float2 unpack2(unsigned long long v) {
    float2 f;
    asm("mov.b64 {%0, %1}, %2;" : "=f"(f.x), "=f"(f.y) : "l"(v));
    return f;
}

// larger value wins; ties -> smaller expert index (matches jax.lax.top_k)
__device__ __forceinline__ unsigned long long sortkey(float v, int e) {
    unsigned u = __float_as_uint(v);
    u = (u & 0x80000000u) ? ~u : (u | 0x80000000u);
    return ((unsigned long long)u << 32) | (unsigned)(63 - e);
}

// Fused: GEMM (x @ W^T) -> logits -> sigmoid/top-8/normalize -> outputs + bincount -> maxvio.
// Grid: 128 blocks (single wave), 128 threads, 8 tok x 8 exp per thread.
__global__ __launch_bounds__(NTHR, 1) void k_gate(
    const float* __restrict__ X,    // [NTOK, CDIM]
    const int* __restrict__ mask,   // [NTOK] bool as int32
    const float* __restrict__ W,    // [NEXP, CDIM]
    const float* __restrict__ gb,   // [NEXP]
    const float* __restrict__ eb,   // [NEXP]
    float* __restrict__ out,        // [NKTOT idx | NKTOT probs | 1 maxvio]
    int pos)
{
    extern __shared__ float smem[];
    __shared__ float sGb[NEXP], sEb[NEXP], sCnt[NEXP];
    __shared__ int sLast;

    float* As = smem;               // [2][BK][APITCH]
    float* Bs = smem + AREG;        // [2][BK][BPITCH]

    const int tid  = threadIdx.x;
    const int lane = tid & 31;
    const int wid  = tid >> 5;
    const int eg   = tid & 7;       // experts eg*8 .. +7
    const int tg   = tid >> 3;      // tokens  tg*8 .. +7
    const int tok0 = blockIdx.x * BM;

    if (tid < NEXP) { sGb[tid] = gb[tid]; sEb[tid] = eb[tid]; sCnt[tid] = 0.f; }

    // global->smem transpose mapping: A 1024 float4/chunk (8/thr), B 512 (4/thr)
    int ar[8], ac[8], br[4], bc[4];
    const float* Ag[8];
    const float* Bg[4];
#pragma unroll
    for (int p = 0; p < 8; p++) {
        int idx = tid + p * NTHR;
        ar[p] = idx >> 3; ac[p] = (idx & 7) * 4;
        Ag[p] = X + (size_t)(tok0 + ar[p]) * CDIM + ac[p];
    }
#pragma unroll
    for (int p = 0; p < 4; p++) {
        int idx = tid + p * NTHR;
        br[p] = idx >> 3; bc[p] = (idx & 7) * 4;
        Bg[p] = W + (size_t)br[p] * CDIM + bc[p];
    }

    // accumulators: 4 token-pairs (f32x2) x 8 experts
    unsigned long long acc[4][8];
#pragma unroll
    for (int i = 0; i < 4; i++)
#pragma unroll
        for (int j = 0; j < 8; j++) acc[i][j] = 0ull;

    // ---- prologue: chunk 0 -> buffer 0 (transposed [k][m]) ----
    {
        float4 a[8], b[4];
#pragma unroll
        for (int p = 0; p < 8; p++) a[p] = *(const float4*)Ag[p];
#pragma unroll
        for (int p = 0; p < 4; p++) b[p] = *(const float4*)Bg[p];
#pragma unroll
        for (int p = 0; p < 8; p++)
#pragma unroll
            for (int c = 0; c < 4; c++)
                As[(ac[p] + c) * APITCH + ar[p]] = ((const float*)&a[p])[c];
#pragma unroll
        for (int p = 0; p < 4; p++)
#pragma unroll
            for (int c = 0; c < 4; c++)
                Bs[(bc[p] + c) * BPITCH + br[p]] = ((const float*)&b[p])[c];
    }
    __syncthreads();

    for (int t = 0; t < NCHUNK; t++) {
        const int cur = t & 1;
        float4 an[8], bn[4];
        if (t + 1 < NCHUNK) {
            const int off = (t + 1) * BK;
#pragma unroll
            for (int p = 0; p < 8; p++) an[p] = *(const float4*)(Ag[p] + off);
#pragma unroll
            for (int p = 0; p < 4; p++) bn[p] = *(const float4*)(Bg[p] + off);
        }

        const float* Ab = As + cur * ABUF + tg * 8;
        const float* Bb = Bs + cur * BBUF + eg * 8;
#pragma unroll
        for (int k = 0; k < BK; k++) {
            ulonglong2 a01 = *(const ulonglong2*)(Ab + k * APITCH);       // tokens 0..3
            ulonglong2 a23 = *(const ulonglong2*)(Ab + k * APITCH + 4);   // tokens 4..7
            float4     bv0 = *(const float4*)(Bb + k * BPITCH);           // experts 0..3
            float4     bv1 = *(const float4*)(Bb + k * BPITCH + 4);       // experts 4..7
            unsigned long long b0 = dup2(bv0.x), b1 = dup2(bv0.y);
            unsigned long long b2 = dup2(bv0.z), b3 = dup2(bv0.w);
            unsigned long long b4 = dup2(bv1.x), b5 = dup2(bv1.y);
            unsigned long long b6 = dup2(bv1.z), b7 = dup2(bv1.w);
            fma2(acc[0][0], a01.x, b0); fma2(acc[0][1], a01.x, b1);
            fma2(acc[0][2], a01.x, b2); fma2(acc[0][3], a01.x, b3);
            fma2(acc[0][4], a01.x, b4); fma2(acc[0][5], a01.x, b5);
            fma2(acc[0][6], a01.x, b6); fma2(acc[0][7], a01.x, b7);
            fma2(acc[1][0], a01.y, b0); fma2(acc[1][1], a01.y, b1);
            fma2(acc[1][2], a01.y, b2); fma2(acc[1][3], a01.y, b3);
            fma2(acc[1][4], a01.y, b4); fma2(acc[1][5], a01.y, b5);
            fma2(acc[1][6], a01.y, b6); fma2(acc[1][7], a01.y, b7);
            fma2(acc[2][0], a23.x, b0); fma2(acc[2][1], a23.x, b1);
            fma2(acc[2][2], a23.x, b2); fma2(acc[2][3], a23.x, b3);
            fma2(acc[2][4], a23.x, b4); fma2(acc[2][5], a23.x, b5);
            fma2(acc[2][6], a23.x, b6); fma2(acc[2][7], a23.x, b7);
            fma2(acc[3][0], a23.y, b0); fma2(acc[3][1], a23.y, b1);
            fma2(acc[3][2], a23.y, b2); fma2(acc[3][3], a23.y, b3);
            fma2(acc[3][4], a23.y, b4); fma2(acc[3][5], a23.y, b5);
            fma2(acc[3][6], a23.y, b6); fma2(acc[3][7], a23.y, b7);
        }

        if (t + 1 < NCHUNK) {
            float* Asn = As + (1 - cur) * ABUF;
            float* Bsn = Bs + (1 - cur) * BBUF;
#pragma unroll
            for (int p = 0; p < 8; p++)
#pragma unroll
                for (int c = 0; c < 4; c++)
                    Asn[(ac[p] + c) * APITCH + ar[p]] = ((const float*)&an[p])[c];
#pragma unroll
            for (int p = 0; p < 4; p++)
#pragma unroll
                for (int c = 0; c < 4; c++)
                    Bsn[(bc[p] + c) * BPITCH + br[p]] = ((const float*)&bn[p])[c];
            __syncthreads();
        }
    }
    __syncthreads();   // GEMM done; smem free for reuse

    // ---- logits tile Ls[m][n], stride 65, +gate_bias ----
    float* Ls = smem;
#pragma unroll
    for (int i = 0; i < 4; i++)
#pragma unroll
        for (int j = 0; j < 8; j++) {
            float2 v = unpack2(acc[i][j]);
            const int n = eg * 8 + j;
            const float b = sGb[n];
            Ls[(tg * 8 + 2 * i + 0) * 65 + n] = v.x + b;
            Ls[(tg * 8 + 2 * i + 1) * 65 + n] = v.y + b;
        }
    __syncthreads();

    // ---- warp-per-token top-8 of 64 (proven epilogue); 4 warps x 32 tokens ----
    const float eb0 = sEb[lane], eb1 = sEb[lane + 32];
    for (int q = 0; q < 32; q++) {
        const int m = wid * 32 + q;
        const int tok = tok0 + m;
        const float* row = Ls + m * 65;
        const float g0 = row[lane], g1 = row[lane + 32];
        const float s0 = g0 + eb0, s1 = g1 + eb1;
        bool u0 = false, u1 = false;
        float selIdx = 0.f, selProb = 0.f;
        const int mk = mask[tok];

#pragma unroll
        for (int it = 0; it < KTOP; it++) {
            unsigned long long k0 = u0 ? 0ull : sortkey(s0, lane);
            unsigned long long k1 = u1 ? 0ull : sortkey(s1, lane + 32);
            unsigned long long key = k0 > k1 ? k0 : k1;
#pragma unroll
            for (int o = 16; o; o >>= 1) {
                unsigned long long oth = __shfl_xor_sync(0xffffffffu, key, o);
                if (oth > key) key = oth;
            }
            const int e = 63 - (int)(key & 63u);
            if (e == lane)      u0 = true;
            if (e == lane + 32) u1 = true;
            if (lane == it) {
                const float g = row[e];
                selIdx = (float)e;
                selProb = 1.f / (1.f + expf(-g));
                if (mk) atomicAdd(&sCnt[e], 1.f);
            }
        }
        float p = (lane < KTOP) ? selProb : 0.f;
        float sum = p;
#pragma unroll
        for (int o = 16; o; o >>= 1) sum += __shfl_xor_sync(0xffffffffu, sum, o);
        if (lane < KTOP) {
            out[(size_t)tok * KTOP + lane]         = selIdx;
            out[NKTOT + (size_t)tok * KTOP + lane] = selProb / sum;
        }
    }

    __syncthreads();
    if (tid < NEXP) {
        const float c = sCnt[tid];
        if (c != 0.f) atomicAdd(&g_counts[tid], c);
    }

    // ---- last block computes maxvio and resets scratch (deterministic) ----
    if (tid == 0) {
        __threadfence();
        sLast = (atomicAdd(&g_done, 1) == (int)gridDim.x - 1) ? 1 : 0;
    }
    __syncthreads();
    if (sLast && wid == 0) {
        float c0 = g_counts[lane], c1 = g_counts[lane + 32];
        float mx = fmaxf(c0, c1);
        float sm = c0 + c1;
#pragma unroll
        for (int o = 16; o; o >>= 1) {
            mx = fmaxf(mx, __shfl_xor_sync(0xffffffffu, mx, o));
            sm += __shfl_xor_sync(0xffffffffu, sm, o);
        }
        if (lane == 0) {
            const float avg = sm / 64.f;
            out[pos] = (mx - avg) / (avg + 1e-5f);
            g_done = 0;
        }
        g_counts[lane] = 0.f;
        g_counts[lane + 32] = 0.f;
    }
}

extern "C" void kernel_launch(void* const* d_in, const int* in_sizes, int n_in,
                              void* d_out, int out_size) {
    const float* X    = (const float*)d_in[0];
    const int*   mask = (const int*)d_in[1];
    const float* W    = (const float*)d_in[2];
    const float* gb   = (const float*)d_in[3];
    const float* eb   = (const float*)d_in[4];
    float*       out  = (float*)d_out;

    cudaFuncSetAttribute(k_gate, cudaFuncAttributeMaxDynamicSharedMemorySize, SMEM_DYN);
    k_gate<<<NTOK / BM, NTHR, SMEM_DYN>>>(X, mask, W, gb, eb, out, out_size - 1);
}

// round 6
// speedup vs baseline: 1.2609x; 1.2609x over previous
#include <cuda_runtime.h>
#include <cstdint>
#include <math.h>

// Problem: B=4, T=4096, C=2048, E=64, K=8
#define NTOK   16384
#define CDIM   2048
#define NEXP   64
#define KTOP   8
#define BM     128
#define BK     32
#define NCHUNK (CDIM / BK)   // 64
#define NKTOT  (NTOK * KTOP)
#define NTHR   256

// smem: A [2][BK][APITCH], B [2][BK][BPITCH]; reused as logits [128][65]
#define APITCH 132
#define BPITCH 68
#define ABUF   (BK * APITCH)             // 4224 floats
#define BBUF   (BK * BPITCH)             // 2176 floats
#define AREG   (2 * ABUF)
#define SMEM_DYN ((AREG + 2 * BBUF) * 4) // 51200 bytes (>= 128*65*4 logits)

__device__ float g_counts[NEXP];
__device__ int   g_done = 0;

// --- packed fp32x2 helpers (B300: scalar FFMA is half-rate; f32x2 is full-rate) ---
__device__ __forceinline__ unsigned long long dup2(float x) {
    unsigned long long r;
    asm("mov.b64 %0, {%1, %1};" : "=l"(r) : "f"(x));
    return r;
}
__device__ __forceinline__ void fma2(unsigned long long& d, unsigned long long a, unsigned long long b) {
    asm("fma.rn.f32x2 %0, %1, %2, %0;" : "+l"(d) : "l"(a), "l"(b));
}
__device__ __forceinline__ float2 unpack2(unsigned long long v) {
    float2 f;
    asm("mov.b64 {%0, %1}, %2;" : "=f"(f.x), "=f"(f.y) : "l"(v));
    return f;
}

// XOR 4-block swizzle: element v (token/expert idx) at k-row u -> storage position.
// Makes transposed STS conflict-free while keeping reads 16B-vectorizable.
__device__ __forceinline__ int swz(int v, int u) {
    return (((v >> 2) ^ (u >> 2)) << 2) | (v & 3);
}

// larger value wins; ties -> smaller expert index (matches jax.lax.top_k)
__device__ __forceinline__ unsigned long long sortkey(float v, int e) {
    unsigned u = __float_as_uint(v);
    u = (u & 0x80000000u) ? ~u : (u | 0x80000000u);
    return ((unsigned long long)u << 32) | (unsigned)(63 - e);
}

// Fused: GEMM (x @ W^T) -> logits -> sigmoid/top-8/normalize -> outputs + bincount -> maxvio.
// Grid: 128 blocks (single wave), 256 threads, 8 tok x 4 exp per thread.
__global__ __launch_bounds__(NTHR, 1) void k_gate(
    const float* __restrict__ X,    // [NTOK, CDIM]
    const int* __restrict__ mask,   // [NTOK] bool as int32
    const float* __restrict__ W,    // [NEXP, CDIM]
    const float* __restrict__ gb,   // [NEXP]
    const float* __restrict__ eb,   // [NEXP]
    float* __restrict__ out,        // [NKTOT idx | NKTOT probs | 1 maxvio]
    int pos)
{
    extern __shared__ float smem[];
    __shared__ float sGb[NEXP], sEb[NEXP], sCnt[NEXP];
    __shared__ int sLast;

    float* As = smem;               // [2][BK][APITCH], swizzled [k][m]
    float* Bs = smem + AREG;        // [2][BK][BPITCH], swizzled [k][n]

    const int tid  = threadIdx.x;
    const int lane = tid & 31;
    const int wid  = tid >> 5;
    const int tx   = tid & 15;      // experts tx*4 .. +3
    const int ty   = tid >> 4;      // tokens  ty*8 .. +7
    const int tok0 = blockIdx.x * BM;

    if (tid < NEXP) { sGb[tid] = gb[tid]; sEb[tid] = eb[tid]; sCnt[tid] = 0.f; }

    // global->smem transpose mapping: A 1024 float4/chunk (4/thr), B 512 (2/thr)
    int ar[4], ac[4], br[2], bc[2];
    const float* Ag[4];
    const float* Bg[2];
#pragma unroll
    for (int p = 0; p < 4; p++) {
        int idx = tid + p * NTHR;
        ar[p] = idx >> 3; ac[p] = (idx & 7) * 4;
        Ag[p] = X + (size_t)(tok0 + ar[p]) * CDIM + ac[p];
    }
#pragma unroll
    for (int p = 0; p < 2; p++) {
        int idx = tid + p * NTHR;
        br[p] = idx >> 3; bc[p] = (idx & 7) * 4;
        Bg[p] = W + (size_t)br[p] * CDIM + bc[p];
    }

    // accumulators: 4 token-pairs (f32x2) x 4 experts
    unsigned long long acc[4][4];
#pragma unroll
    for (int i = 0; i < 4; i++)
#pragma unroll
        for (int j = 0; j < 4; j++) acc[i][j] = 0ull;

    // ---- prologue: chunk 0 -> buffer 0 (swizzled transpose) ----
    {
        float4 a[4], b[2];
#pragma unroll
        for (int p = 0; p < 4; p++) a[p] = *(const float4*)Ag[p];
#pragma unroll
        for (int p = 0; p < 2; p++) b[p] = *(const float4*)Bg[p];
#pragma unroll
        for (int p = 0; p < 4; p++)
#pragma unroll
            for (int c = 0; c < 4; c++) {
                const int u = ac[p] + c;
                As[u * APITCH + swz(ar[p], u)] = ((const float*)&a[p])[c];
            }
#pragma unroll
        for (int p = 0; p < 2; p++)
#pragma unroll
            for (int c = 0; c < 4; c++) {
                const int u = bc[p] + c;
                Bs[u * BPITCH + swz(br[p], u)] = ((const float*)&b[p])[c];
            }
    }
    __syncthreads();

    for (int t = 0; t < NCHUNK; t++) {
        const int cur = t & 1;
        float4 an[4], bn[2];
        if (t + 1 < NCHUNK) {
            const int off = (t + 1) * BK;
#pragma unroll
            for (int p = 0; p < 4; p++) an[p] = *(const float4*)(Ag[p] + off);
#pragma unroll
            for (int p = 0; p < 2; p++) bn[p] = *(const float4*)(Bg[p] + off);
        }

        const float* Ab = As + cur * ABUF;
        const float* Bb = Bs + cur * BBUF;
#pragma unroll
        for (int k = 0; k < BK; k++) {
            const int s = k >> 2;
            ulonglong2 a01 = *(const ulonglong2*)(Ab + k * APITCH + (((2 * ty)     ^ s) << 2));
            ulonglong2 a23 = *(const ulonglong2*)(Ab + k * APITCH + (((2 * ty + 1) ^ s) << 2));
            float4     bv  = *(const float4*)    (Bb + k * BPITCH + ((tx ^ s) << 2));
            unsigned long long b0 = dup2(bv.x), b1 = dup2(bv.y);
            unsigned long long b2 = dup2(bv.z), b3 = dup2(bv.w);
            fma2(acc[0][0], a01.x, b0); fma2(acc[0][1], a01.x, b1);
            fma2(acc[0][2], a01.x, b2); fma2(acc[0][3], a01.x, b3);
            fma2(acc[1][0], a01.y, b0); fma2(acc[1][1], a01.y, b1);
            fma2(acc[1][2], a01.y, b2); fma2(acc[1][3], a01.y, b3);
            fma2(acc[2][0], a23.x, b0); fma2(acc[2][1], a23.x, b1);
            fma2(acc[2][2], a23.x, b2); fma2(acc[2][3], a23.x, b3);
            fma2(acc[3][0], a23.y, b0); fma2(acc[3][1], a23.y, b1);
            fma2(acc[3][2], a23.y, b2); fma2(acc[3][3], a23.y, b3);
        }

        if (t + 1 < NCHUNK) {
            float* Asn = As + (1 - cur) * ABUF;
            float* Bsn = Bs + (1 - cur) * BBUF;
#pragma unroll
            for (int p = 0; p < 4; p++)
#pragma unroll
                for (int c = 0; c < 4; c++) {
                    const int u = ac[p] + c;
                    Asn[u * APITCH + swz(ar[p], u)] = ((const float*)&an[p])[c];
                }
#pragma unroll
            for (int p = 0; p < 2; p++)
#pragma unroll
                for (int c = 0; c < 4; c++) {
                    const int u = bc[p] + c;
                    Bsn[u * BPITCH + swz(br[p], u)] = ((const float*)&bn[p])[c];
                }
            __syncthreads();
        }
    }
    __syncthreads();   // GEMM done; smem free for reuse

    // ---- logits tile Ls[m][n], stride 65, +gate_bias ----
    float* Ls = smem;
#pragma unroll
    for (int i = 0; i < 4; i++)
#pragma unroll
        for (int j = 0; j < 4; j++) {
            float2 v = unpack2(acc[i][j]);
            const int n = tx * 4 + j;
            const float b = sGb[n];
            Ls[(ty * 8 + 2 * i + 0) * 65 + n] = v.x + b;
            Ls[(ty * 8 + 2 * i + 1) * 65 + n] = v.y + b;
        }
    __syncthreads();

    // ---- warp-per-token top-8 of 64 (proven epilogue); 8 warps x 16 tokens ----
    const float eb0 = sEb[lane], eb1 = sEb[lane + 32];
    for (int q = 0; q < 16; q++) {
        const int m = wid * 16 + q;
        const int tok = tok0 + m;
        const float* row = Ls + m * 65;
        const float g0 = row[lane], g1 = row[lane + 32];
        const float s0 = g0 + eb0, s1 = g1 + eb1;
        bool u0 = false, u1 = false;
        float selIdx = 0.f, selProb = 0.f;
        const int mk = mask[tok];

#pragma unroll
        for (int it = 0; it < KTOP; it++) {
            unsigned long long k0 = u0 ? 0ull : sortkey(s0, lane);
            unsigned long long k1 = u1 ? 0ull : sortkey(s1, lane + 32);
            unsigned long long key = k0 > k1 ? k0 : k1;
#pragma unroll
            for (int o = 16; o; o >>= 1) {
                unsigned long long oth = __shfl_xor_sync(0xffffffffu, key, o);
                if (oth > key) key = oth;
            }
            const int e = 63 - (int)(key & 63u);
            if (e == lane)      u0 = true;
            if (e == lane + 32) u1 = true;
            if (lane == it) {
                const float g = row[e];
                selIdx = (float)e;
                selProb = 1.f / (1.f + expf(-g));
                if (mk) atomicAdd(&sCnt[e], 1.f);
            }
        }
        float p = (lane < KTOP) ? selProb : 0.f;
        float sum = p;
#pragma unroll
        for (int o = 16; o; o >>= 1) sum += __shfl_xor_sync(0xffffffffu, sum, o);
        if (lane < KTOP) {
            out[(size_t)tok * KTOP + lane]         = selIdx;
            out[NKTOT + (size_t)tok * KTOP + lane] = selProb / sum;
        }
    }

    __syncthreads();
    if (tid < NEXP) {
        const float c = sCnt[tid];
        if (c != 0.f) atomicAdd(&g_counts[tid], c);
    }

    // ---- last block computes maxvio and resets scratch (deterministic) ----
    if (tid == 0) {
        __threadfence();
        sLast = (atomicAdd(&g_done, 1) == (int)gridDim.x - 1) ? 1 : 0;
    }
    __syncthreads();
    if (sLast && wid == 0) {
        float c0 = g_counts[lane], c1 = g_counts[lane + 32];
        float mx = fmaxf(c0, c1);
        float sm = c0 + c1;
#pragma unroll
        for (int o = 16; o; o >>= 1) {
            mx = fmaxf(mx, __shfl_xor_sync(0xffffffffu, mx, o));
            sm += __shfl_xor_sync(0xffffffffu, sm, o);
        }
        if (lane == 0) {
            const float avg = sm / 64.f;
            out[pos] = (mx - avg) / (avg + 1e-5f);
            g_done = 0;
        }
        g_counts[lane] = 0.f;
        g_counts[lane + 32] = 0.f;
    }
}

extern "C" void kernel_launch(void* const* d_in, const int* in_sizes, int n_in,
                              void* d_out, int out_size) {
    const float* X    = (const float*)d_in[0];
    const int*   mask = (const int*)d_in[1];
    const float* W    = (const float*)d_in[2];
    const float* gb   = (const float*)d_in[3];
    const float* eb   = (const float*)d_in[4];
    float*       out  = (float*)d_out;

    cudaFuncSetAttribute(k_gate, cudaFuncAttributeMaxDynamicSharedMemorySize, SMEM_DYN);
    k_gate<<<NTOK / BM, NTHR, SMEM_DYN>>>(X, mask, W, gb, eb, out, out_size - 1);
}

// round 7
// speedup vs baseline: 1.5567x; 1.2346x over previous
#include <cuda_runtime.h>
#include <cstdint>
#include <math.h>

// Problem: B=4, T=4096, C=2048, E=64, K=8
#define NTOK   16384
#define CDIM   2048
#define NEXP   64
#define KTOP   8
#define BM     128
#define BK     32
#define NCHUNK (CDIM / BK)   // 64
#define NKTOT  (NTOK * KTOP)
#define NTHR   512

// smem: A [2][BK][APITCH], B [2][BK][BPITCH]; reused as logits [128][65]
#define APITCH 132
#define BPITCH 68
#define ABUF   (BK * APITCH)             // 4224 floats
#define BBUF   (BK * BPITCH)             // 2176 floats
#define AREG   (2 * ABUF)
#define SMEM_DYN ((AREG + 2 * BBUF) * 4) // 51200 bytes (>= 128*65*4 logits)

__device__ float g_counts[NEXP];
__device__ int   g_done = 0;

// --- packed fp32x2 helpers (B300: scalar FFMA is half-rate; f32x2 is full-rate) ---
__device__ __forceinline__ unsigned long long dup2(float x) {
    unsigned long long r;
    asm("mov.b64 %0, {%1, %1};" : "=l"(r) : "f"(x));
    return r;
}
__device__ __forceinline__ void fma2(unsigned long long& d, unsigned long long a, unsigned long long b) {
    asm("fma.rn.f32x2 %0, %1, %2, %0;" : "+l"(d) : "l"(a), "l"(b));
}
__device__ __forceinline__ float2 unpack2(unsigned long long v) {
    float2 f;
    asm("mov.b64 {%0, %1}, %2;" : "=f"(f.x), "=f"(f.y) : "l"(v));
    return f;
}

// XOR 4-block swizzle: element v at k-row u -> storage position (conflict-free STS,
// reads stay 16B-vectorizable).
__device__ __forceinline__ int swz(int v, int u) {
    return (((v >> 2) ^ (u >> 2)) << 2) | (v & 3);
}

// larger value wins; ties -> smaller expert index (matches jax.lax.top_k)
__device__ __forceinline__ unsigned long long sortkey(float v, int e) {
    unsigned u = __float_as_uint(v);
    u = (u & 0x80000000u) ? ~u : (u | 0x80000000u);
    return ((unsigned long long)u << 32) | (unsigned)(63 - e);
}

// Fused: GEMM (x @ W^T) -> logits -> sigmoid/top-8/normalize -> outputs + bincount -> maxvio.
// Grid: 128 blocks (1/SM), 512 threads (4 warps/SMSP), 4 tok x 4 exp per thread.
__global__ __launch_bounds__(NTHR, 1) void k_gate(
    const float* __restrict__ X,    // [NTOK, CDIM]
    const int* __restrict__ mask,   // [NTOK] bool as int32
    const float* __restrict__ W,    // [NEXP, CDIM]
    const float* __restrict__ gb,   // [NEXP]
    const float* __restrict__ eb,   // [NEXP]
    float* __restrict__ out,        // [NKTOT idx | NKTOT probs | 1 maxvio]
    int pos)
{
    extern __shared__ float smem[];
    __shared__ float sGb[NEXP], sEb[NEXP], sCnt[NEXP];
    __shared__ int sLast;

    float* As = smem;               // [2][BK][APITCH], swizzled [k][m]
    float* Bs = smem + AREG;        // [2][BK][BPITCH], swizzled [k][n]

    const int tid  = threadIdx.x;
    const int lane = tid & 31;
    const int wid  = tid >> 5;
    const int tx   = tid & 15;      // experts tx*4 .. +3
    const int ty   = tid >> 4;      // tokens  ty*4 .. +3  (0..31)
    const int tok0 = blockIdx.x * BM;

    if (tid < NEXP) { sGb[tid] = gb[tid]; sEb[tid] = eb[tid]; sCnt[tid] = 0.f; }

    // global->smem transpose mapping: A 1024 float4/chunk (2/thr), B 512 (1/thr)
    int ar[2], ac[2];
    const float* Ag[2];
#pragma unroll
    for (int p = 0; p < 2; p++) {
        int idx = tid + p * NTHR;
        ar[p] = idx >> 3; ac[p] = (idx & 7) * 4;
        Ag[p] = X + (size_t)(tok0 + ar[p]) * CDIM + ac[p];
    }
    const int br = tid >> 3, bc = (tid & 7) * 4;
    const float* Bg = W + (size_t)br * CDIM + bc;

    // accumulators: 2 token-pairs (f32x2) x 4 experts
    unsigned long long acc[2][4];
#pragma unroll
    for (int i = 0; i < 2; i++)
#pragma unroll
        for (int j = 0; j < 4; j++) acc[i][j] = 0ull;

    // ---- prologue: chunk 0 -> buffer 0 (swizzled transpose) ----
    {
        float4 a[2], b;
#pragma unroll
        for (int p = 0; p < 2; p++) a[p] = *(const float4*)Ag[p];
        b = *(const float4*)Bg;
#pragma unroll
        for (int p = 0; p < 2; p++)
#pragma unroll
            for (int c = 0; c < 4; c++) {
                const int u = ac[p] + c;
                As[u * APITCH + swz(ar[p], u)] = ((const float*)&a[p])[c];
            }
#pragma unroll
        for (int c = 0; c < 4; c++) {
            const int u = bc + c;
            Bs[u * BPITCH + swz(br, u)] = ((const float*)&b)[c];
        }
    }
    __syncthreads();

    for (int t = 0; t < NCHUNK; t++) {
        const int cur = t & 1;
        float4 an[2], bn;
        if (t + 1 < NCHUNK) {
            const int off = (t + 1) * BK;
#pragma unroll
            for (int p = 0; p < 2; p++) an[p] = *(const float4*)(Ag[p] + off);
            bn = *(const float4*)(Bg + off);
        }

        const float* Ab = As + cur * ABUF;
        const float* Bb = Bs + cur * BBUF;
#pragma unroll
        for (int k = 0; k < BK; k++) {
            const int s = k >> 2;
            ulonglong2 a01 = *(const ulonglong2*)(Ab + k * APITCH + ((ty ^ s) << 2));  // 4 tokens
            float4     bv  = *(const float4*)    (Bb + k * BPITCH + ((tx ^ s) << 2));  // 4 experts
            unsigned long long b0 = dup2(bv.x), b1 = dup2(bv.y);
            unsigned long long b2 = dup2(bv.z), b3 = dup2(bv.w);
            fma2(acc[0][0], a01.x, b0); fma2(acc[0][1], a01.x, b1);
            fma2(acc[0][2], a01.x, b2); fma2(acc[0][3], a01.x, b3);
            fma2(acc[1][0], a01.y, b0); fma2(acc[1][1], a01.y, b1);
            fma2(acc[1][2], a01.y, b2); fma2(acc[1][3], a01.y, b3);
        }

        if (t + 1 < NCHUNK) {
            float* Asn = As + (1 - cur) * ABUF;
            float* Bsn = Bs + (1 - cur) * BBUF;
#pragma unroll
            for (int p = 0; p < 2; p++)
#pragma unroll
                for (int c = 0; c < 4; c++) {
                    const int u = ac[p] + c;
                    Asn[u * APITCH + swz(ar[p], u)] = ((const float*)&an[p])[c];
                }
#pragma unroll
            for (int c = 0; c < 4; c++) {
                const int u = bc + c;
                Bsn[u * BPITCH + swz(br, u)] = ((const float*)&bn)[c];
            }
            __syncthreads();
        }
    }
    __syncthreads();   // GEMM done; smem free for reuse

    // ---- logits tile Ls[m][n], stride 65, +gate_bias ----
    float* Ls = smem;
#pragma unroll
    for (int i = 0; i < 2; i++)
#pragma unroll
        for (int j = 0; j < 4; j++) {
            float2 v = unpack2(acc[i][j]);
            const int n = tx * 4 + j;
            const float b = sGb[n];
            Ls[(ty * 4 + 2 * i + 0) * 65 + n] = v.x + b;
            Ls[(ty * 4 + 2 * i + 1) * 65 + n] = v.y + b;
        }
    __syncthreads();

    // ---- warp-per-token top-8 of 64 (proven epilogue); 16 warps x 8 tokens ----
    const float eb0 = sEb[lane], eb1 = sEb[lane + 32];
    for (int q = 0; q < 8; q++) {
        const int m = wid * 8 + q;
        const int tok = tok0 + m;
        const float* row = Ls + m * 65;
        const float g0 = row[lane], g1 = row[lane + 32];
        const float s0 = g0 + eb0, s1 = g1 + eb1;
        bool u0 = false, u1 = false;
        float selIdx = 0.f, selProb = 0.f;
        const int mk = mask[tok];

#pragma unroll
        for (int it = 0; it < KTOP; it++) {
            unsigned long long k0 = u0 ? 0ull : sortkey(s0, lane);
            unsigned long long k1 = u1 ? 0ull : sortkey(s1, lane + 32);
            unsigned long long key = k0 > k1 ? k0 : k1;
#pragma unroll
            for (int o = 16; o; o >>= 1) {
                unsigned long long oth = __shfl_xor_sync(0xffffffffu, key, o);
                if (oth > key) key = oth;
            }
            const int e = 63 - (int)(key & 63u);
            if (e == lane)      u0 = true;
            if (e == lane + 32) u1 = true;
            if (lane == it) {
                const float g = row[e];
                selIdx = (float)e;
                selProb = 1.f / (1.f + expf(-g));
                if (mk) atomicAdd(&sCnt[e], 1.f);
            }
        }
        float p = (lane < KTOP) ? selProb : 0.f;
        float sum = p;
#pragma unroll
        for (int o = 16; o; o >>= 1) sum += __shfl_xor_sync(0xffffffffu, sum, o);
        if (lane < KTOP) {
            out[(size_t)tok * KTOP + lane]         = selIdx;
            out[NKTOT + (size_t)tok * KTOP + lane] = selProb / sum;
        }
    }

    __syncthreads();
    if (tid < NEXP) {
        const float c = sCnt[tid];
        if (c != 0.f) atomicAdd(&g_counts[tid], c);
    }

    // ---- last block computes maxvio and resets scratch (deterministic) ----
    if (tid == 0) {
        __threadfence();
        sLast = (atomicAdd(&g_done, 1) == (int)gridDim.x - 1) ? 1 : 0;
    }
    __syncthreads();
    if (sLast && wid == 0) {
        float c0 = g_counts[lane], c1 = g_counts[lane + 32];
        float mx = fmaxf(c0, c1);
        float sm = c0 + c1;
#pragma unroll
        for (int o = 16; o; o >>= 1) {
            mx = fmaxf(mx, __shfl_xor_sync(0xffffffffu, mx, o));
            sm += __shfl_xor_sync(0xffffffffu, sm, o);
        }
        if (lane == 0) {
            const float avg = sm / 64.f;
            out[pos] = (mx - avg) / (avg + 1e-5f);
            g_done = 0;
        }
        g_counts[lane] = 0.f;
        g_counts[lane + 32] = 0.f;
    }
}

extern "C" void kernel_launch(void* const* d_in, const int* in_sizes, int n_in,
                              void* d_out, int out_size) {
    const float* X    = (const float*)d_in[0];
    const int*   mask = (const int*)d_in[1];
    const float* W    = (const float*)d_in[2];
    const float* gb   = (const float*)d_in[3];
    const float* eb   = (const float*)d_in[4];
    float*       out  = (float*)d_out;

    cudaFuncSetAttribute(k_gate, cudaFuncAttributeMaxDynamicSharedMemorySize, SMEM_DYN);
    k_gate<<<NTOK / BM, NTHR, SMEM_DYN>>>(X, mask, W, gb, eb, out, out_size - 1);
}